// round 10
// baseline (speedup 1.0000x reference)
#include <cuda_runtime.h>
#include <math_constants.h>

#define BB 512
#define TT 512
#define KK 64

// 16.7 MB history scratch (argmax index per (b, t, j)), plus per-batch best-last tag.
__device__ unsigned char g_hist[(size_t)BB * TT * KK];
__device__ int g_best[BB];

// ---------------------------------------------------------------------------
// Forward Viterbi: block = 64 threads = one batch; thread j owns next-tag j.
// ONE __syncthreads per time step.
//   - scores double-buffered in shared (LDS-broadcast gathers), also in reg.
//   - live prev-tag set: 64-bit mask from two per-warp ballots.
//   - threshold base = OWN-warp max (5-level shfl butterfly over registers).
//     warpmax <= global smax, so the kept set is a SUPERSET of the exact
//     pruned set -> pruning stays exact. A pruned i has, for every j,
//     (s_i + T_ij) < (s_k + T_kj) - 0.05 in real arithmetic (k = score max);
//     0.05 >> 4 ulp(|s|~2000) ~ 1e-3, so i can never be the argmax, not even
//     via first-index ties.
//   - argmax: extract live indices ascending (ffsll), 2 per trip into two
//     interleaved strict-'>' chains; merge picks (greater value) else
//     (equal value, smaller index) -> exact jnp.argmax first-occurrence.
// ---------------------------------------------------------------------------
__global__ __launch_bounds__(KK, 8) void viterbi_forward(
    const float* __restrict__ emissions,   // [B, T, K]
    const int*   __restrict__ mask,        // [B, T]
    const float* __restrict__ start_t,     // [K]
    const float* __restrict__ end_t,       // [K]
    const float* __restrict__ trans)       // [K, K]
{
    const int b    = blockIdx.x;
    const int j    = threadIdx.x;
    const int w    = j >> 5;
    const int lane = j & 31;

    __shared__ __align__(16) float tsh[KK * KK];     // trans[i][j] at i*64+j (16 KB)
    __shared__ __align__(16) float score_sh[2][KK];  // double-buffered scores
    __shared__ unsigned balsh[2][2];                 // [parity][warp]
    __shared__ float red_sh[4];

    const float* em = emissions + (size_t)b * TT * KK;
    const int*   mk = mask + (size_t)b * TT;

    // ---- one-time: stage trans (coalesced), global Tmin/Tmax ----
    float tmn = CUDART_INF_F, tmx = -CUDART_INF_F;
    for (int r = 0; r < KK; ++r) {
        const int idx = r * KK + j;
        const float v = trans[idx];
        tsh[idx] = v;
        tmn = fminf(tmn, v);
        tmx = fmaxf(tmx, v);
    }
#pragma unroll
    for (int d = 16; d; d >>= 1) {
        tmn = fminf(tmn, __shfl_xor_sync(0xFFFFFFFFu, tmn, d));
        tmx = fmaxf(tmx, __shfl_xor_sync(0xFFFFFFFFu, tmx, d));
    }
    if (lane == 0) { red_sh[w] = tmn; red_sh[2 + w] = tmx; }
    __syncthreads();
    const float thrD =
        (fminf(red_sh[0], red_sh[1]) - fmaxf(red_sh[2], red_sh[3])) - 0.05f;

    // ---- init scores (t = 0) ----
    float s = start_t[j] + em[j];
    score_sh[0][j] = s;
    {
        float wm = s;
#pragma unroll
        for (int d = 16; d; d >>= 1)
            wm = fmaxf(wm, __shfl_xor_sync(0xFFFFFFFFu, wm, d));
        const unsigned bal = __ballot_sync(0xFFFFFFFFu, s >= wm + thrD);
        if (lane == 0) balsh[0][w] = bal;
    }
    __syncthreads();
    unsigned long long mlive =
        (unsigned long long)balsh[0][0] | ((unsigned long long)balsh[0][1] << 32);

    // ---- prefetch (depth 2): emissions (own tag) + mask (broadcast) ----
    float e_cur = em[KK + j];
    float e_nxt = em[2 * KK + j];
    int   mc    = mk[1];
    int   mnx   = mk[2];

    unsigned char* hp = g_hist + ((size_t)b * TT + 1) * KK;

    int p = 0;
    for (int t = 1; t < TT; ++t) {
        // branch-free prefetch of step t+2 (clamped at tail)
        const int tpf = (t + 2 < TT) ? (t + 2) : (TT - 1);
        const float e_pf = em[tpf * KK + j];
        const int   mpf  = mk[tpf];

        const float e = e_cur;
        const float* sc = score_sh[p];

        // ---- argmax over live prev-tags: 2 interleaved strict-'>' chains ----
        float bA = -CUDART_INF_F, bB = -CUDART_INF_F;
        int   iA = 0,             iB = 0;
        unsigned long long m = mlive;             // warp-uniform
        while (m) {
            const int i1 = __ffsll((long long)m) - 1;
            m &= m - 1;
            const int i2 = m ? (__ffsll((long long)m) - 1) : i1;  // dup-pad
            m &= m - 1;
            const float v1 = (sc[i1] + tsh[i1 * KK + j]) + e;
            const float v2 = (sc[i2] + tsh[i2 * KK + j]) + e;
            const bool g1 = v1 > bA;
            bA = g1 ? v1 : bA;  iA = g1 ? i1 : iA;
            const bool g2 = v2 > bB;
            bB = g2 ? v2 : bB;  iB = g2 ? i2 : iB;
        }
        // merge: greater value wins; on equal values the smaller index wins
        // (both chains ascend, so this reproduces global first-index argmax).
        const bool pickB = (bB > bA) || ((bB == bA) && (iB < iA));
        const float bst = pickB ? bB : bA;
        const int   bid = pickB ? iB : iA;

        // history always records the argmax; mask only gates the score.
        hp[j] = (unsigned char)bid;
        s = mc ? bst : s;
        score_sh[p ^ 1][j] = s;

        // ---- own-warp threshold + ballots (no extra barrier) ----
        float wm = s;
#pragma unroll
        for (int d = 16; d; d >>= 1)
            wm = fmaxf(wm, __shfl_xor_sync(0xFFFFFFFFu, wm, d));
        const unsigned bal = __ballot_sync(0xFFFFFFFFu, s >= wm + thrD);
        if (lane == 0) balsh[p ^ 1][w] = bal;

        __syncthreads();   // orders: score STS, ballot STS vs next reads
        mlive = (unsigned long long)balsh[p ^ 1][0] |
                ((unsigned long long)balsh[p ^ 1][1] << 32);

        p ^= 1;
        hp += KK;
        e_cur = e_nxt; e_nxt = e_pf;
        mc    = mnx;   mnx   = mpf;
    }

    // ---- final: + end_transitions, first-index argmax over j ----
    score_sh[0][j] = s;
    __syncthreads();
    if (j == 0) {
        float bv = score_sh[0][0] + end_t[0];
        int   bi = 0;
#pragma unroll
        for (int i = 1; i < KK; ++i) {
            const float f = score_sh[0][i] + end_t[i];
            if (f > bv) { bv = f; bi = i; }
        }
        g_best[b] = bi;
    }
}

// ---------------------------------------------------------------------------
// Backtrace: one block per batch. Stage the 32KB history slab + mask into
// shared, then one thread walks the dependent chain at LDS latency.
// Output tags written as FLOAT32 (harness output dtype).
// ---------------------------------------------------------------------------
__global__ __launch_bounds__(256) void viterbi_backtrace(
    const int*  __restrict__ mask,   // [B, T]
    float*      __restrict__ out)    // [B, T] float32 tags
{
    const int b = blockIdx.x;
    __shared__ unsigned char h[TT * KK];   // 32 KB
    __shared__ int msk[TT];                // 2 KB

    const uint4* src = (const uint4*)(g_hist + (size_t)b * TT * KK);
    uint4* dst = (uint4*)h;
#pragma unroll 4
    for (int k = threadIdx.x; k < (TT * KK) / 16; k += blockDim.x)
        dst[k] = src[k];
    for (int t = threadIdx.x; t < TT; t += blockDim.x)
        msk[t] = mask[b * TT + t];
    __syncthreads();

    if (threadIdx.x == 0) {
        int tag = g_best[b];
        out[b * TT + (TT - 1)] = (float)tag;
        for (int t = TT - 1; t >= 1; --t) {
            const int prev = h[t * KK + tag];
            tag = msk[t] ? prev : tag;
            out[b * TT + t - 1] = (float)tag;
        }
    }
}

extern "C" void kernel_launch(void* const* d_in, const int* in_sizes, int n_in,
                              void* d_out, int out_size)
{
    // Bind inputs by element count:
    //   16777216 -> emissions, 262144 -> attn_mask, 4096 -> transitions,
    //   64 -> start_transitions (first), end_transitions (second)
    const float* emissions = nullptr;
    const int*   attn_mask = nullptr;
    const float* start_t   = nullptr;
    const float* end_t     = nullptr;
    const float* trans     = nullptr;

    for (int i = 0; i < n_in; ++i) {
        const int sz = in_sizes[i];
        if (sz == BB * TT * KK)      emissions = (const float*)d_in[i];
        else if (sz == BB * TT)      attn_mask = (const int*)d_in[i];
        else if (sz == KK * KK)      trans     = (const float*)d_in[i];
        else if (sz == KK) {
            if (!start_t) start_t = (const float*)d_in[i];
            else          end_t   = (const float*)d_in[i];
        }
    }

    float* out = (float*)d_out;  // [512,512] float32 tag values

    viterbi_forward<<<BB, KK>>>(emissions, attn_mask, start_t, end_t, trans);
    viterbi_backtrace<<<BB, 256>>>(attn_mask, out);
}

// round 11
// speedup vs baseline: 1.3578x; 1.3578x over previous
#include <cuda_runtime.h>
#include <math_constants.h>

#define BB 512
#define TT 512
#define KK 64

// 16.7 MB history scratch (argmax index per (b, t, j)), plus per-batch best-last tag.
__device__ unsigned char g_hist[(size_t)BB * TT * KK];
__device__ int g_best[BB];

// ---------------------------------------------------------------------------
// Forward Viterbi: one WARP per batch, 4 warps/block sharing the trans tile.
// Lane l owns next-tags j0=l, j1=l+32 (scores in registers AND shared).
//   - live prev-tag set: compacted ASCENDING index list in shared (int4
//     groups, sentinel idx=64 with score -inf / trans 0), rebuilt each step
//     warp-synchronously from two ballots (popc positions). Double-buffered;
//     ONE __syncwarp per step, zero __syncthreads in the time loop.
//   - exact pruning: i prunable iff s_i < smax + (Tmin - Tmax) - 0.05 where
//     smax is the TRUE 64-tag max (butterfly over fmaxf(s0,s1)). Margin >>
//     accumulated rounding (~1e-3), so a pruned i can never be the argmax,
//     not even via first-index ties.
//   - argmax: single strict-'>' chain per j over the ascending list -> exact
//     jnp.argmax first-occurrence semantics.
// ---------------------------------------------------------------------------
__global__ __launch_bounds__(128) void viterbi_forward(
    const float* __restrict__ emissions,   // [B, T, K]
    const int*   __restrict__ mask,        // [B, T]
    const float* __restrict__ start_t,     // [K]
    const float* __restrict__ end_t,       // [K]
    const float* __restrict__ trans)       // [K, K]
{
    const int tid  = threadIdx.x;
    const int lane = tid & 31;
    const int w    = tid >> 5;
    const int b    = blockIdx.x * 4 + w;

    __shared__ __align__(16) float2 tp_sh[KK + 1][32];      // row 64 = zeros
    __shared__ __align__(16) float  score_sh[4][2][72];     // [64] = -inf
    __shared__ __align__(16) int    live_sh[4][2][72];      // ascending + pads
    __shared__ float red_sh[8];

    // ---- one-time: stage trans (pair layout), global Tmin/Tmax ----
    float tmn = CUDART_INF_F, tmx = -CUDART_INF_F;
    for (int i = w; i < KK; i += 4) {
        const float a = trans[i * KK + lane];
        const float c = trans[i * KK + 32 + lane];
        tp_sh[i][lane] = make_float2(a, c);
        tmn = fminf(tmn, fminf(a, c));
        tmx = fmaxf(tmx, fmaxf(a, c));
    }
    if (w == 0) tp_sh[KK][lane] = make_float2(0.0f, 0.0f);   // sentinel row
    if (lane == 0) {
        score_sh[w][0][KK] = -CUDART_INF_F;                  // sentinel scores
        score_sh[w][1][KK] = -CUDART_INF_F;
    }
#pragma unroll
    for (int d = 16; d; d >>= 1) {
        tmn = fminf(tmn, __shfl_xor_sync(0xFFFFFFFFu, tmn, d));
        tmx = fmaxf(tmx, __shfl_xor_sync(0xFFFFFFFFu, tmx, d));
    }
    if (lane == 0) { red_sh[w] = tmn; red_sh[4 + w] = tmx; }
    __syncthreads();                                          // last block-wide sync
    const float mn = fminf(fminf(red_sh[0], red_sh[1]), fminf(red_sh[2], red_sh[3]));
    const float mx = fmaxf(fmaxf(red_sh[4], red_sh[5]), fmaxf(red_sh[6], red_sh[7]));
    const float thrD = (mn - mx) - 0.05f;

    const float* em = emissions + (size_t)b * TT * KK;
    const int*   mk = mask + (size_t)b * TT;
    const unsigned lanemask = (1u << lane) - 1u;

    // ---- init scores (t = 0) + initial live list into buffer 0 ----
    float s0 = start_t[lane]      + em[lane];
    float s1 = start_t[lane + 32] + em[lane + 32];
    int nl;
    {
        float wm = fmaxf(s0, s1);
#pragma unroll
        for (int d = 16; d; d >>= 1)
            wm = fmaxf(wm, __shfl_xor_sync(0xFFFFFFFFu, wm, d));
        const float thr = wm + thrD;
        const unsigned b0 = __ballot_sync(0xFFFFFFFFu, s0 >= thr);
        const unsigned b1 = __ballot_sync(0xFFFFFFFFu, s1 >= thr);
        nl = __popc(b0) + __popc(b1);
        score_sh[w][0][lane]      = s0;
        score_sh[w][0][lane + 32] = s1;
        if ((b0 >> lane) & 1u)
            live_sh[w][0][__popc(b0 & lanemask)] = lane;
        if ((b1 >> lane) & 1u)
            live_sh[w][0][__popc(b0) + __popc(b1 & lanemask)] = lane + 32;
        if (lane < 4) live_sh[w][0][nl + lane] = KK;          // sentinel pads
        __syncwarp();
    }

    // ---- prefetch (depth 2): emissions + mask ----
    float e0c = em[KK + lane],      e1c = em[KK + 32 + lane];
    float e0n = em[2 * KK + lane],  e1n = em[2 * KK + 32 + lane];
    int   mc  = mk[1];
    int   mnx = mk[2];

    unsigned char* hp = g_hist + ((size_t)b * TT + 1) * KK;

    int p = 0;
    for (int t = 1; t < TT; ++t) {
        // branch-free prefetch of step t+2 (clamped at tail)
        const int tpf = (t + 2 < TT) ? (t + 2) : (TT - 1);
        const float e0p = em[tpf * KK + lane];
        const float e1p = em[tpf * KK + 32 + lane];
        const int   mpf = mk[tpf];

        // ---- phase A: argmax over compacted live list (ascending) ----
        const float* sc = score_sh[w][p];
        const int4*  lv = (const int4*)live_sh[w][p];
        const int ng = (nl + 3) >> 2;

        float bst0 = -CUDART_INF_F, bst1 = -CUDART_INF_F;
        int   bid0 = 0,             bid1 = 0;
        for (int g = 0; g < ng; ++g) {
            const int4 iv = lv[g];
            const float  sa = sc[iv.x], sb = sc[iv.y];
            const float  scq = sc[iv.z], sd = sc[iv.w];
            const float2 ta = tp_sh[iv.x][lane];
            const float2 tb = tp_sh[iv.y][lane];
            const float2 tc = tp_sh[iv.z][lane];
            const float2 td = tp_sh[iv.w][lane];
            const float va0 = (sa + ta.x) + e0c, va1 = (sa + ta.y) + e1c;
            const float vb0 = (sb + tb.x) + e0c, vb1 = (sb + tb.y) + e1c;
            const float vc0 = (scq + tc.x) + e0c, vc1 = (scq + tc.y) + e1c;
            const float vd0 = (sd + td.x) + e0c, vd1 = (sd + td.y) + e1c;
            const bool a0 = va0 > bst0; bst0 = a0 ? va0 : bst0; bid0 = a0 ? iv.x : bid0;
            const bool a1 = va1 > bst1; bst1 = a1 ? va1 : bst1; bid1 = a1 ? iv.x : bid1;
            const bool c0 = vb0 > bst0; bst0 = c0 ? vb0 : bst0; bid0 = c0 ? iv.y : bid0;
            const bool c1 = vb1 > bst1; bst1 = c1 ? vb1 : bst1; bid1 = c1 ? iv.y : bid1;
            const bool d0 = vc0 > bst0; bst0 = d0 ? vc0 : bst0; bid0 = d0 ? iv.z : bid0;
            const bool d1 = vc1 > bst1; bst1 = d1 ? vc1 : bst1; bid1 = d1 ? iv.z : bid1;
            const bool f0 = vd0 > bst0; bst0 = f0 ? vd0 : bst0; bid0 = f0 ? iv.w : bid0;
            const bool f1 = vd1 > bst1; bst1 = f1 ? vd1 : bst1; bid1 = f1 ? iv.w : bid1;
        }

        // history always records the argmax; mask only gates the score.
        hp[lane]      = (unsigned char)bid0;
        hp[lane + 32] = (unsigned char)bid1;

        s0 = mc ? bst0 : s0;
        s1 = mc ? bst1 : s1;

        // ---- exact 64-wide max -> threshold -> ballots -> list (p^1) ----
        float wm = fmaxf(s0, s1);
#pragma unroll
        for (int d = 16; d; d >>= 1)
            wm = fmaxf(wm, __shfl_xor_sync(0xFFFFFFFFu, wm, d));
        const float thr = wm + thrD;
        const unsigned bb0 = __ballot_sync(0xFFFFFFFFu, s0 >= thr);
        const unsigned bb1 = __ballot_sync(0xFFFFFFFFu, s1 >= thr);
        nl = __popc(bb0) + __popc(bb1);

        const int q = p ^ 1;
        score_sh[w][q][lane]      = s0;
        score_sh[w][q][lane + 32] = s1;
        if ((bb0 >> lane) & 1u)
            live_sh[w][q][__popc(bb0 & lanemask)] = lane;
        if ((bb1 >> lane) & 1u)
            live_sh[w][q][__popc(bb0) + __popc(bb1 & lanemask)] = lane + 32;
        if (lane < 4) live_sh[w][q][nl + lane] = KK;          // sentinel pads
        __syncwarp();

        p = q;
        hp += KK;
        e0c = e0n; e1c = e1n; e0n = e0p; e1n = e1p;
        mc  = mnx; mnx = mpf;
    }

    // ---- final: + end_transitions, first-index argmax over all 64 tags ----
    {
        const float v0 = s0 + end_t[lane];
        const float v1 = s1 + end_t[lane + 32];
        float bv; int bi;
        if (v1 > v0) { bv = v1; bi = lane + 32; }
        else         { bv = v0; bi = lane; }
#pragma unroll
        for (int d = 16; d; d >>= 1) {
            const float vo = __shfl_xor_sync(0xFFFFFFFFu, bv, d);
            const int   io = __shfl_xor_sync(0xFFFFFFFFu, bi, d);
            if (vo > bv || (vo == bv && io < bi)) { bv = vo; bi = io; }
        }
        if (lane == 0) g_best[b] = bi;
    }
}

// ---------------------------------------------------------------------------
// Backtrace: one block per batch. Stage the 32KB history slab + mask into
// shared, then one thread walks the dependent chain at LDS latency.
// Output tags written as FLOAT32 (harness output dtype).
// ---------------------------------------------------------------------------
__global__ __launch_bounds__(256) void viterbi_backtrace(
    const int*  __restrict__ mask,   // [B, T]
    float*      __restrict__ out)    // [B, T] float32 tags
{
    const int b = blockIdx.x;
    __shared__ unsigned char h[TT * KK];   // 32 KB
    __shared__ int msk[TT];                // 2 KB

    const uint4* src = (const uint4*)(g_hist + (size_t)b * TT * KK);
    uint4* dst = (uint4*)h;
#pragma unroll 4
    for (int k = threadIdx.x; k < (TT * KK) / 16; k += blockDim.x)
        dst[k] = src[k];
    for (int t = threadIdx.x; t < TT; t += blockDim.x)
        msk[t] = mask[b * TT + t];
    __syncthreads();

    if (threadIdx.x == 0) {
        int tag = g_best[b];
        out[b * TT + (TT - 1)] = (float)tag;
        for (int t = TT - 1; t >= 1; --t) {
            const int prev = h[t * KK + tag];
            tag = msk[t] ? prev : tag;
            out[b * TT + t - 1] = (float)tag;
        }
    }
}

extern "C" void kernel_launch(void* const* d_in, const int* in_sizes, int n_in,
                              void* d_out, int out_size)
{
    // Bind inputs by element count:
    //   16777216 -> emissions, 262144 -> attn_mask, 4096 -> transitions,
    //   64 -> start_transitions (first), end_transitions (second)
    const float* emissions = nullptr;
    const int*   attn_mask = nullptr;
    const float* start_t   = nullptr;
    const float* end_t     = nullptr;
    const float* trans     = nullptr;

    for (int i = 0; i < n_in; ++i) {
        const int sz = in_sizes[i];
        if (sz == BB * TT * KK)      emissions = (const float*)d_in[i];
        else if (sz == BB * TT)      attn_mask = (const int*)d_in[i];
        else if (sz == KK * KK)      trans     = (const float*)d_in[i];
        else if (sz == KK) {
            if (!start_t) start_t = (const float*)d_in[i];
            else          end_t   = (const float*)d_in[i];
        }
    }

    float* out = (float*)d_out;  // [512,512] float32 tag values

    viterbi_forward<<<BB / 4, 128>>>(emissions, attn_mask, start_t, end_t, trans);
    viterbi_backtrace<<<BB, 256>>>(attn_mask, out);
}

// round 13
// speedup vs baseline: 1.8979x; 1.3978x over previous
#include <cuda_runtime.h>
#include <math_constants.h>

#define BB 512
#define TT 512
#define KK 64

// 16.7 MB history scratch (argmax index per (b, t, j)), plus per-batch best-last tag.
__device__ unsigned char g_hist[(size_t)BB * TT * KK];
__device__ int g_best[BB];

// ---------------------------------------------------------------------------
// cp.async helpers (LDGSTS on sm_103): 16B global->shared, grouped.
// ---------------------------------------------------------------------------
__device__ __forceinline__ void cp_async16(void* smem_dst, const void* gsrc) {
    unsigned saddr = (unsigned)__cvta_generic_to_shared(smem_dst);
    asm volatile("cp.async.ca.shared.global [%0], [%1], 16;"
                 :: "r"(saddr), "l"(gsrc));
}
__device__ __forceinline__ void cp_commit() {
    asm volatile("cp.async.commit_group;");
}
__device__ __forceinline__ void cp_wait1() {
    asm volatile("cp.async.wait_group 1;");
}

// ---------------------------------------------------------------------------
// Forward Viterbi: one WARP per batch, 4 warps/block sharing the trans tile.
// Lane l owns next-tags j0=l, j1=l+32.
//   - emissions delivered via double-buffered cp.async tiles (8 steps = 2KB
//     per warp), issued 8 steps ahead -> DRAM latency fully off the per-step
//     dependency chain (the hidden ~300 cy/step cost of rounds 3-11).
//   - per-step e read from shared, prefetched 1 step ahead; mask row staged
//     to shared once at init.
//   - live prev-tag set: compacted ASCENDING index list in shared (int4
//     groups, sentinel idx=64 with score -inf / trans 0), rebuilt each step
//     from two ballots (popc positions). Double-buffered; ONE __syncwarp per
//     step, zero __syncthreads in the time loop.
//   - exact pruning: i prunable iff s_i < smax + (Tmin - Tmax) - 0.05 where
//     smax is the TRUE 64-tag max (butterfly). Margin >> accumulated rounding
//     (~1e-3), so a pruned i can never be the argmax, even via ties.
//   - argmax: single strict-'>' chain per j over the ascending list -> exact
//     jnp.argmax first-occurrence semantics.
// ---------------------------------------------------------------------------
__global__ __launch_bounds__(128) void viterbi_forward(
    const float* __restrict__ emissions,   // [B, T, K]
    const int*   __restrict__ mask,        // [B, T]
    const float* __restrict__ start_t,     // [K]
    const float* __restrict__ end_t,       // [K]
    const float* __restrict__ trans)       // [K, K]
{
    const int tid  = threadIdx.x;
    const int lane = tid & 31;
    const int w    = tid >> 5;
    const int b    = blockIdx.x * 4 + w;

    __shared__ __align__(16) float2 tp_sh[KK + 1][32];      // row 64 = zeros
    __shared__ __align__(16) float  score_sh[4][2][72];     // [64] = -inf
    __shared__ __align__(16) int    live_sh[4][2][72];      // ascending + pads
    __shared__ __align__(16) float  em_sh[4][2][8 * KK];    // emission tiles
    __shared__ int   smask_sh[4][TT];
    __shared__ float red_sh[8];

    const float* em = emissions + (size_t)b * TT * KK;
    const int*   mk = mask + (size_t)b * TT;

    // ---- issue first two emission tiles immediately (overlap with staging) ----
    {
        float* dst0 = &em_sh[w][0][0];
        const float* src0 = em;                  // steps [0,8)
#pragma unroll
        for (int k = 0; k < 4; ++k)
            cp_async16(dst0 + k * 128 + lane * 4, src0 + k * 128 + lane * 4);
        cp_commit();
        float* dst1 = &em_sh[w][1][0];
        const float* src1 = em + 8 * KK;         // steps [8,16)
#pragma unroll
        for (int k = 0; k < 4; ++k)
            cp_async16(dst1 + k * 128 + lane * 4, src1 + k * 128 + lane * 4);
        cp_commit();
    }

    // ---- one-time: stage trans (pair layout) + mask row, global Tmin/Tmax ----
    float tmn = CUDART_INF_F, tmx = -CUDART_INF_F;
    for (int i = w; i < KK; i += 4) {
        const float a = trans[i * KK + lane];
        const float c = trans[i * KK + 32 + lane];
        tp_sh[i][lane] = make_float2(a, c);
        tmn = fminf(tmn, fminf(a, c));
        tmx = fmaxf(tmx, fmaxf(a, c));
    }
    if (w == 0) tp_sh[KK][lane] = make_float2(0.0f, 0.0f);   // sentinel row
    if (lane == 0) {
        score_sh[w][0][KK] = -CUDART_INF_F;                  // sentinel scores
        score_sh[w][1][KK] = -CUDART_INF_F;
    }
    for (int k = lane; k < TT; k += 32) smask_sh[w][k] = mk[k];
#pragma unroll
    for (int d = 16; d; d >>= 1) {
        tmn = fminf(tmn, __shfl_xor_sync(0xFFFFFFFFu, tmn, d));
        tmx = fmaxf(tmx, __shfl_xor_sync(0xFFFFFFFFu, tmx, d));
    }
    if (lane == 0) { red_sh[w] = tmn; red_sh[4 + w] = tmx; }
    __syncthreads();                                          // last block-wide sync
    const float mn = fminf(fminf(red_sh[0], red_sh[1]), fminf(red_sh[2], red_sh[3]));
    const float mx = fmaxf(fmaxf(red_sh[4], red_sh[5]), fmaxf(red_sh[6], red_sh[7]));
    const float thrD = (mn - mx) - 0.05f;

    const unsigned lanemask = (1u << lane) - 1u;

    // ---- tile 0 ready ----
    cp_wait1();
    __syncwarp();
    int ebuf = 0;

    // ---- init scores (t = 0) + initial live list into buffer 0 ----
    float s0 = start_t[lane]      + em_sh[w][0][lane];
    float s1 = start_t[lane + 32] + em_sh[w][0][32 + lane];
    int nl;
    {
        float wm = fmaxf(s0, s1);
#pragma unroll
        for (int d = 16; d; d >>= 1)
            wm = fmaxf(wm, __shfl_xor_sync(0xFFFFFFFFu, wm, d));
        const float thr = wm + thrD;
        const unsigned b0 = __ballot_sync(0xFFFFFFFFu, s0 >= thr);
        const unsigned b1 = __ballot_sync(0xFFFFFFFFu, s1 >= thr);
        nl = __popc(b0) + __popc(b1);
        score_sh[w][0][lane]      = s0;
        score_sh[w][0][lane + 32] = s1;
        if ((b0 >> lane) & 1u)
            live_sh[w][0][__popc(b0 & lanemask)] = lane;
        if ((b1 >> lane) & 1u)
            live_sh[w][0][__popc(b0) + __popc(b1 & lanemask)] = lane + 32;
        if (lane < 4) live_sh[w][0][nl + lane] = KK;          // sentinel pads
        __syncwarp();
    }

    // ---- e / mask for t = 1 (from shared) ----
    float e0c = em_sh[w][0][KK + lane];
    float e1c = em_sh[w][0][KK + 32 + lane];
    int   mc  = smask_sh[w][1];

    unsigned char* hp = g_hist + ((size_t)b * TT + 1) * KK;

    int p = 0;
    for (int t = 1; t < TT; ++t) {
        // ---- tile boundary: t+1 enters a new 8-step tile ----
        if ((t & 7) == 7) {
            const int nbase = (t + 9 <= TT - 8) ? (t + 9) : (TT - 8);
            float* dst = &em_sh[w][ebuf][0];     // vacated buffer
            const float* src = em + (size_t)nbase * KK;
#pragma unroll
            for (int k = 0; k < 4; ++k)
                cp_async16(dst + k * 128 + lane * 4, src + k * 128 + lane * 4);
            cp_commit();
            cp_wait1();                          // tile containing t+1 complete
            __syncwarp();
            ebuf ^= 1;
        }

        // ---- phase A: argmax over compacted live list (ascending) ----
        const float* sc = score_sh[w][p];
        const int4*  lv = (const int4*)live_sh[w][p];
        const int ng = (nl + 3) >> 2;

        float bst0 = -CUDART_INF_F, bst1 = -CUDART_INF_F;
        int   bid0 = 0,             bid1 = 0;
        for (int g = 0; g < ng; ++g) {
            const int4 iv = lv[g];
            const float  sa = sc[iv.x], sb = sc[iv.y];
            const float  scq = sc[iv.z], sd = sc[iv.w];
            const float2 ta = tp_sh[iv.x][lane];
            const float2 tb = tp_sh[iv.y][lane];
            const float2 tc = tp_sh[iv.z][lane];
            const float2 td = tp_sh[iv.w][lane];
            const float va0 = (sa + ta.x) + e0c, va1 = (sa + ta.y) + e1c;
            const float vb0 = (sb + tb.x) + e0c, vb1 = (sb + tb.y) + e1c;
            const float vc0 = (scq + tc.x) + e0c, vc1 = (scq + tc.y) + e1c;
            const float vd0 = (sd + td.x) + e0c, vd1 = (sd + td.y) + e1c;
            const bool a0 = va0 > bst0; bst0 = a0 ? va0 : bst0; bid0 = a0 ? iv.x : bid0;
            const bool a1 = va1 > bst1; bst1 = a1 ? va1 : bst1; bid1 = a1 ? iv.x : bid1;
            const bool c0 = vb0 > bst0; bst0 = c0 ? vb0 : bst0; bid0 = c0 ? iv.y : bid0;
            const bool c1 = vb1 > bst1; bst1 = c1 ? vb1 : bst1; bid1 = c1 ? iv.y : bid1;
            const bool d0 = vc0 > bst0; bst0 = d0 ? vc0 : bst0; bid0 = d0 ? iv.z : bid0;
            const bool d1 = vc1 > bst1; bst1 = d1 ? vc1 : bst1; bid1 = d1 ? iv.z : bid1;
            const bool f0 = vd0 > bst0; bst0 = f0 ? vd0 : bst0; bid0 = f0 ? iv.w : bid0;
            const bool f1 = vd1 > bst1; bst1 = f1 ? vd1 : bst1; bid1 = f1 ? iv.w : bid1;
        }

        // history always records the argmax; mask only gates the score.
        hp[lane]      = (unsigned char)bid0;
        hp[lane + 32] = (unsigned char)bid1;

        s0 = mc ? bst0 : s0;
        s1 = mc ? bst1 : s1;

        // ---- exact 64-wide max -> threshold -> ballots -> list (p^1) ----
        float wm = fmaxf(s0, s1);
#pragma unroll
        for (int d = 16; d; d >>= 1)
            wm = fmaxf(wm, __shfl_xor_sync(0xFFFFFFFFu, wm, d));
        const float thr = wm + thrD;
        const unsigned bb0 = __ballot_sync(0xFFFFFFFFu, s0 >= thr);
        const unsigned bb1 = __ballot_sync(0xFFFFFFFFu, s1 >= thr);
        nl = __popc(bb0) + __popc(bb1);

        const int q = p ^ 1;
        score_sh[w][q][lane]      = s0;
        score_sh[w][q][lane + 32] = s1;
        if ((bb0 >> lane) & 1u)
            live_sh[w][q][__popc(bb0 & lanemask)] = lane;
        if ((bb1 >> lane) & 1u)
            live_sh[w][q][__popc(bb0) + __popc(bb1 & lanemask)] = lane + 32;
        if (lane < 4) live_sh[w][q][nl + lane] = KK;          // sentinel pads
        __syncwarp();

        // ---- prefetch e / mask for t+1 from shared (1 step of slack) ----
        const int tn  = (t + 1 < TT) ? (t + 1) : (TT - 1);
        const int off = (tn & 7) * KK;
        e0c = em_sh[w][ebuf][off + lane];
        e1c = em_sh[w][ebuf][off + 32 + lane];
        mc  = smask_sh[w][tn];

        p = q;
        hp += KK;
    }

    // ---- final: + end_transitions, first-index argmax over all 64 tags ----
    {
        const float v0 = s0 + end_t[lane];
        const float v1 = s1 + end_t[lane + 32];
        float bv; int bi;
        if (v1 > v0) { bv = v1; bi = lane + 32; }
        else         { bv = v0; bi = lane; }
#pragma unroll
        for (int d = 16; d; d >>= 1) {
            const float vo = __shfl_xor_sync(0xFFFFFFFFu, bv, d);
            const int   io = __shfl_xor_sync(0xFFFFFFFFu, bi, d);
            if (vo > bv || (vo == bv && io < bi)) { bv = vo; bi = io; }
        }
        if (lane == 0) g_best[b] = bi;
    }
}

// ---------------------------------------------------------------------------
// Backtrace: one block per batch. Stage the 32KB history slab + mask into
// shared, then one thread walks the dependent chain at LDS latency.
// Output tags written as FLOAT32 (harness output dtype).
// ---------------------------------------------------------------------------
__global__ __launch_bounds__(256) void viterbi_backtrace(
    const int*  __restrict__ mask,   // [B, T]
    float*      __restrict__ out)    // [B, T] float32 tags
{
    const int b = blockIdx.x;
    __shared__ unsigned char h[TT * KK];   // 32 KB
    __shared__ int msk[TT];                // 2 KB

    const uint4* src = (const uint4*)(g_hist + (size_t)b * TT * KK);
    uint4* dst = (uint4*)h;
#pragma unroll 4
    for (int k = threadIdx.x; k < (TT * KK) / 16; k += blockDim.x)
        dst[k] = src[k];
    for (int t = threadIdx.x; t < TT; t += blockDim.x)
        msk[t] = mask[b * TT + t];
    __syncthreads();

    if (threadIdx.x == 0) {
        int tag = g_best[b];
        out[b * TT + (TT - 1)] = (float)tag;
        for (int t = TT - 1; t >= 1; --t) {
            const int prev = h[t * KK + tag];
            tag = msk[t] ? prev : tag;
            out[b * TT + t - 1] = (float)tag;
        }
    }
}

extern "C" void kernel_launch(void* const* d_in, const int* in_sizes, int n_in,
                              void* d_out, int out_size)
{
    // Bind inputs by element count:
    //   16777216 -> emissions, 262144 -> attn_mask, 4096 -> transitions,
    //   64 -> start_transitions (first), end_transitions (second)
    const float* emissions = nullptr;
    const int*   attn_mask = nullptr;
    const float* start_t   = nullptr;
    const float* end_t     = nullptr;
    const float* trans     = nullptr;

    for (int i = 0; i < n_in; ++i) {
        const int sz = in_sizes[i];
        if (sz == BB * TT * KK)      emissions = (const float*)d_in[i];
        else if (sz == BB * TT)      attn_mask = (const int*)d_in[i];
        else if (sz == KK * KK)      trans     = (const float*)d_in[i];
        else if (sz == KK) {
            if (!start_t) start_t = (const float*)d_in[i];
            else          end_t   = (const float*)d_in[i];
        }
    }

    float* out = (float*)d_out;  // [512,512] float32 tag values

    viterbi_forward<<<BB / 4, 128>>>(emissions, attn_mask, start_t, end_t, trans);
    viterbi_backtrace<<<BB, 256>>>(attn_mask, out);
}

// round 14
// speedup vs baseline: 2.2544x; 1.1878x over previous
#include <cuda_runtime.h>
#include <math_constants.h>

#define BB 512
#define TT 512
#define KK 64

// 16.7 MB history scratch (argmax index per (b, t, j)), plus per-batch best-last tag.
__device__ unsigned char g_hist[(size_t)BB * TT * KK];
__device__ int g_best[BB];

// ---------------------------------------------------------------------------
// cp.async helpers (LDGSTS on sm_103): 16B global->shared, grouped.
// ---------------------------------------------------------------------------
__device__ __forceinline__ void cp_async16(void* smem_dst, const void* gsrc) {
    unsigned saddr = (unsigned)__cvta_generic_to_shared(smem_dst);
    asm volatile("cp.async.ca.shared.global [%0], [%1], 16;"
                 :: "r"(saddr), "l"(gsrc));
}
__device__ __forceinline__ void cp_commit() {
    asm volatile("cp.async.commit_group;");
}
__device__ __forceinline__ void cp_wait1() {
    asm volatile("cp.async.wait_group 1;");
}

// ---------------------------------------------------------------------------
// Warp-wide exact f32 max via ONE integer redux (sm_80+: redux.sync.max.u32).
// Order-preserving monotonic float->u32 key; exact inverse on the result.
// (redux.f32 does not exist on sm_103 — R7 lesson.)
// ---------------------------------------------------------------------------
__device__ __forceinline__ float warp_max_f32_redux(float v) {
    const int i = __float_as_int(v);
    const unsigned key = (i >= 0) ? ((unsigned)i | 0x80000000u)
                                  : (unsigned)(~i);
    unsigned r;
    asm("redux.sync.max.u32 %0, %1, 0xffffffff;" : "=r"(r) : "r"(key));
    const int j = (r & 0x80000000u) ? (int)(r & 0x7FFFFFFFu) : ~(int)r;
    return __int_as_float(j);
}

// ---------------------------------------------------------------------------
// Forward Viterbi: one WARP per batch, 4 warps/block sharing the trans tile.
// Lane l owns next-tags j0=l, j1=l+32.
//   - emissions via double-buffered cp.async tiles (8 steps = 2KB per warp),
//     issued 8 steps ahead -> DRAM latency off the per-step chain (R13 win).
//   - warp max via single redux.sync.max.u32 (saves ~100 cy/step vs 5-shfl
//     butterfly).
//   - live prev-tag set: compacted ASCENDING index list in shared (int4
//     groups, sentinel idx=64 with score -inf / trans 0), rebuilt each step
//     from two ballots (popc positions). Double-buffered; ONE __syncwarp per
//     step, zero __syncthreads in the time loop.
//   - exact pruning: i prunable iff s_i < smax + (Tmin - Tmax) - 0.05 where
//     smax is the TRUE 64-tag max. Margin >> accumulated rounding (~1e-3),
//     so a pruned i can never be the argmax, even via first-index ties.
//   - argmax: single strict-'>' chain per j over the ascending list -> exact
//     jnp.argmax first-occurrence semantics.
// ---------------------------------------------------------------------------
__global__ __launch_bounds__(128) void viterbi_forward(
    const float* __restrict__ emissions,   // [B, T, K]
    const int*   __restrict__ mask,        // [B, T]
    const float* __restrict__ start_t,     // [K]
    const float* __restrict__ end_t,       // [K]
    const float* __restrict__ trans)       // [K, K]
{
    const int tid  = threadIdx.x;
    const int lane = tid & 31;
    const int w    = tid >> 5;
    const int b    = blockIdx.x * 4 + w;

    __shared__ __align__(16) float2 tp_sh[KK + 1][32];      // row 64 = zeros
    __shared__ __align__(16) float  score_sh[4][2][72];     // [64] = -inf
    __shared__ __align__(16) int    live_sh[4][2][72];      // ascending + pads
    __shared__ __align__(16) float  em_sh[4][2][8 * KK];    // emission tiles
    __shared__ int   smask_sh[4][TT];
    __shared__ float red_sh[8];

    const float* em = emissions + (size_t)b * TT * KK;
    const int*   mk = mask + (size_t)b * TT;

    // ---- issue first two emission tiles immediately (overlap with staging) ----
    {
        float* dst0 = &em_sh[w][0][0];
        const float* src0 = em;                  // steps [0,8)
#pragma unroll
        for (int k = 0; k < 4; ++k)
            cp_async16(dst0 + k * 128 + lane * 4, src0 + k * 128 + lane * 4);
        cp_commit();
        float* dst1 = &em_sh[w][1][0];
        const float* src1 = em + 8 * KK;         // steps [8,16)
#pragma unroll
        for (int k = 0; k < 4; ++k)
            cp_async16(dst1 + k * 128 + lane * 4, src1 + k * 128 + lane * 4);
        cp_commit();
    }

    // ---- one-time: stage trans (pair layout) + mask row, global Tmin/Tmax ----
    float tmn = CUDART_INF_F, tmx = -CUDART_INF_F;
    for (int i = w; i < KK; i += 4) {
        const float a = trans[i * KK + lane];
        const float c = trans[i * KK + 32 + lane];
        tp_sh[i][lane] = make_float2(a, c);
        tmn = fminf(tmn, fminf(a, c));
        tmx = fmaxf(tmx, fmaxf(a, c));
    }
    if (w == 0) tp_sh[KK][lane] = make_float2(0.0f, 0.0f);   // sentinel row
    if (lane == 0) {
        score_sh[w][0][KK] = -CUDART_INF_F;                  // sentinel scores
        score_sh[w][1][KK] = -CUDART_INF_F;
    }
    for (int k = lane; k < TT; k += 32) smask_sh[w][k] = mk[k];
#pragma unroll
    for (int d = 16; d; d >>= 1) {
        tmn = fminf(tmn, __shfl_xor_sync(0xFFFFFFFFu, tmn, d));
        tmx = fmaxf(tmx, __shfl_xor_sync(0xFFFFFFFFu, tmx, d));
    }
    if (lane == 0) { red_sh[w] = tmn; red_sh[4 + w] = tmx; }
    __syncthreads();                                          // last block-wide sync
    const float mn = fminf(fminf(red_sh[0], red_sh[1]), fminf(red_sh[2], red_sh[3]));
    const float mx = fmaxf(fmaxf(red_sh[4], red_sh[5]), fmaxf(red_sh[6], red_sh[7]));
    const float thrD = (mn - mx) - 0.05f;

    const unsigned lanemask = (1u << lane) - 1u;

    // ---- tile 0 ready ----
    cp_wait1();
    __syncwarp();
    int ebuf = 0;

    // ---- init scores (t = 0) + initial live list into buffer 0 ----
    float s0 = start_t[lane]      + em_sh[w][0][lane];
    float s1 = start_t[lane + 32] + em_sh[w][0][32 + lane];
    int nl;
    {
        const float thr = warp_max_f32_redux(fmaxf(s0, s1)) + thrD;
        const unsigned b0 = __ballot_sync(0xFFFFFFFFu, s0 >= thr);
        const unsigned b1 = __ballot_sync(0xFFFFFFFFu, s1 >= thr);
        nl = __popc(b0) + __popc(b1);
        score_sh[w][0][lane]      = s0;
        score_sh[w][0][lane + 32] = s1;
        if ((b0 >> lane) & 1u)
            live_sh[w][0][__popc(b0 & lanemask)] = lane;
        if ((b1 >> lane) & 1u)
            live_sh[w][0][__popc(b0) + __popc(b1 & lanemask)] = lane + 32;
        if (lane < 4) live_sh[w][0][nl + lane] = KK;          // sentinel pads
        __syncwarp();
    }

    // ---- e / mask for t = 1 (from shared) ----
    float e0c = em_sh[w][0][KK + lane];
    float e1c = em_sh[w][0][KK + 32 + lane];
    int   mc  = smask_sh[w][1];

    unsigned char* hp = g_hist + ((size_t)b * TT + 1) * KK;

    int p = 0;
    for (int t = 1; t < TT; ++t) {
        // ---- tile boundary: t+1 enters a new 8-step tile ----
        if ((t & 7) == 7) {
            const int nbase = (t + 9 <= TT - 8) ? (t + 9) : (TT - 8);
            float* dst = &em_sh[w][ebuf][0];     // vacated buffer
            const float* src = em + (size_t)nbase * KK;
#pragma unroll
            for (int k = 0; k < 4; ++k)
                cp_async16(dst + k * 128 + lane * 4, src + k * 128 + lane * 4);
            cp_commit();
            cp_wait1();                          // tile containing t+1 complete
            __syncwarp();
            ebuf ^= 1;
        }

        // ---- phase A: argmax over compacted live list (ascending) ----
        const float* sc = score_sh[w][p];
        const int4*  lv = (const int4*)live_sh[w][p];
        const int ng = (nl + 3) >> 2;

        float bst0 = -CUDART_INF_F, bst1 = -CUDART_INF_F;
        int   bid0 = 0,             bid1 = 0;
        for (int g = 0; g < ng; ++g) {
            const int4 iv = lv[g];
            const float  sa = sc[iv.x], sb = sc[iv.y];
            const float  scq = sc[iv.z], sd = sc[iv.w];
            const float2 ta = tp_sh[iv.x][lane];
            const float2 tb = tp_sh[iv.y][lane];
            const float2 tc = tp_sh[iv.z][lane];
            const float2 td = tp_sh[iv.w][lane];
            const float va0 = (sa + ta.x) + e0c, va1 = (sa + ta.y) + e1c;
            const float vb0 = (sb + tb.x) + e0c, vb1 = (sb + tb.y) + e1c;
            const float vc0 = (scq + tc.x) + e0c, vc1 = (scq + tc.y) + e1c;
            const float vd0 = (sd + td.x) + e0c, vd1 = (sd + td.y) + e1c;
            const bool a0 = va0 > bst0; bst0 = a0 ? va0 : bst0; bid0 = a0 ? iv.x : bid0;
            const bool a1 = va1 > bst1; bst1 = a1 ? va1 : bst1; bid1 = a1 ? iv.x : bid1;
            const bool c0 = vb0 > bst0; bst0 = c0 ? vb0 : bst0; bid0 = c0 ? iv.y : bid0;
            const bool c1 = vb1 > bst1; bst1 = c1 ? vb1 : bst1; bid1 = c1 ? iv.y : bid1;
            const bool d0 = vc0 > bst0; bst0 = d0 ? vc0 : bst0; bid0 = d0 ? iv.z : bid0;
            const bool d1 = vc1 > bst1; bst1 = d1 ? vc1 : bst1; bid1 = d1 ? iv.z : bid1;
            const bool f0 = vd0 > bst0; bst0 = f0 ? vd0 : bst0; bid0 = f0 ? iv.w : bid0;
            const bool f1 = vd1 > bst1; bst1 = f1 ? vd1 : bst1; bid1 = f1 ? iv.w : bid1;
        }

        // history always records the argmax; mask only gates the score.
        hp[lane]      = (unsigned char)bid0;
        hp[lane + 32] = (unsigned char)bid1;

        s0 = mc ? bst0 : s0;
        s1 = mc ? bst1 : s1;

        // ---- exact 64-wide max (one redux) -> threshold -> ballots -> list ----
        const float thr = warp_max_f32_redux(fmaxf(s0, s1)) + thrD;
        const unsigned bb0 = __ballot_sync(0xFFFFFFFFu, s0 >= thr);
        const unsigned bb1 = __ballot_sync(0xFFFFFFFFu, s1 >= thr);
        nl = __popc(bb0) + __popc(bb1);

        const int q = p ^ 1;
        score_sh[w][q][lane]      = s0;
        score_sh[w][q][lane + 32] = s1;
        if ((bb0 >> lane) & 1u)
            live_sh[w][q][__popc(bb0 & lanemask)] = lane;
        if ((bb1 >> lane) & 1u)
            live_sh[w][q][__popc(bb0) + __popc(bb1 & lanemask)] = lane + 32;
        if (lane < 4) live_sh[w][q][nl + lane] = KK;          // sentinel pads
        __syncwarp();

        // ---- prefetch e / mask for t+1 from shared (1 step of slack) ----
        const int tn  = (t + 1 < TT) ? (t + 1) : (TT - 1);
        const int off = (tn & 7) * KK;
        e0c = em_sh[w][ebuf][off + lane];
        e1c = em_sh[w][ebuf][off + 32 + lane];
        mc  = smask_sh[w][tn];

        p = q;
        hp += KK;
    }

    // ---- final: + end_transitions, first-index argmax over all 64 tags ----
    {
        const float v0 = s0 + end_t[lane];
        const float v1 = s1 + end_t[lane + 32];
        float bv; int bi;
        if (v1 > v0) { bv = v1; bi = lane + 32; }
        else         { bv = v0; bi = lane; }
#pragma unroll
        for (int d = 16; d; d >>= 1) {
            const float vo = __shfl_xor_sync(0xFFFFFFFFu, bv, d);
            const int   io = __shfl_xor_sync(0xFFFFFFFFu, bi, d);
            if (vo > bv || (vo == bv && io < bi)) { bv = vo; bi = io; }
        }
        if (lane == 0) g_best[b] = bi;
    }
}

// ---------------------------------------------------------------------------
// Backtrace: one block per batch. Stage the 32KB history slab + mask into
// shared, then one thread walks the dependent chain at LDS latency.
// Output tags written as FLOAT32 (harness output dtype).
// ---------------------------------------------------------------------------
__global__ __launch_bounds__(256) void viterbi_backtrace(
    const int*  __restrict__ mask,   // [B, T]
    float*      __restrict__ out)    // [B, T] float32 tags
{
    const int b = blockIdx.x;
    __shared__ unsigned char h[TT * KK];   // 32 KB
    __shared__ int msk[TT];                // 2 KB

    const uint4* src = (const uint4*)(g_hist + (size_t)b * TT * KK);
    uint4* dst = (uint4*)h;
#pragma unroll 4
    for (int k = threadIdx.x; k < (TT * KK) / 16; k += blockDim.x)
        dst[k] = src[k];
    for (int t = threadIdx.x; t < TT; t += blockDim.x)
        msk[t] = mask[b * TT + t];
    __syncthreads();

    if (threadIdx.x == 0) {
        int tag = g_best[b];
        out[b * TT + (TT - 1)] = (float)tag;
        for (int t = TT - 1; t >= 1; --t) {
            const int prev = h[t * KK + tag];
            tag = msk[t] ? prev : tag;
            out[b * TT + t - 1] = (float)tag;
        }
    }
}

extern "C" void kernel_launch(void* const* d_in, const int* in_sizes, int n_in,
                              void* d_out, int out_size)
{
    // Bind inputs by element count:
    //   16777216 -> emissions, 262144 -> attn_mask, 4096 -> transitions,
    //   64 -> start_transitions (first), end_transitions (second)
    const float* emissions = nullptr;
    const int*   attn_mask = nullptr;
    const float* start_t   = nullptr;
    const float* end_t     = nullptr;
    const float* trans     = nullptr;

    for (int i = 0; i < n_in; ++i) {
        const int sz = in_sizes[i];
        if (sz == BB * TT * KK)      emissions = (const float*)d_in[i];
        else if (sz == BB * TT)      attn_mask = (const int*)d_in[i];
        else if (sz == KK * KK)      trans     = (const float*)d_in[i];
        else if (sz == KK) {
            if (!start_t) start_t = (const float*)d_in[i];
            else          end_t   = (const float*)d_in[i];
        }
    }

    float* out = (float*)d_out;  // [512,512] float32 tag values

    viterbi_forward<<<BB / 4, 128>>>(emissions, attn_mask, start_t, end_t, trans);
    viterbi_backtrace<<<BB, 256>>>(attn_mask, out);
}